// round 17
// baseline (speedup 1.0000x reference)
#include <cuda_runtime.h>
#include <cstdint>

// Transitive closure of {0} under (left,right) == reference's 8192-step fixed
// point. One-CTA BFS-until-converged, atomic-free.
// R16 confirmed the loop's per-round SERIAL CHAIN dominates. This round:
//   - SPECULATIVE READ: next round's LDS.128 is issued BEFORE bar.red and
//     consumed after it -> 29cyc LDS latency hides under the barrier.
//     Termination weakened to TWO consecutive quiet rounds (a byte written in
//     round t is barrier-drained, so its owner's read issued in t+1 sees it;
//     two consecutive quiet rounds with pending work are impossible).
//   - prologue smem exchange removed: BFS threads LDG their own children
//     directly (4+4 LDG.128), pack leaf->DUMMY offsets into 16 regs.
//   - rest = R16 shape: 512 BFS threads + 512 sleepers (named barriers),
//     byte map, idempotent stores, branchless SEL+STS expansion.

#define NNODES    8192
#define NTHREADS  1024
#define NBFS      512
#define DUMMY     NNODES
#define DONE_ALL  0x0101010101010101ull

__global__ __launch_bounds__(NTHREADS, 1)
void DAGGenome_reach_kernel(const int* __restrict__ left,
                            const int* __restrict__ right,
                            float* __restrict__ out)
{
    __shared__ __align__(16) unsigned char reach8[NNODES + 16];   // +DUMMY pad

    const int tid = threadIdx.x;

    // --- init byte map (one u64 store per thread) + pad, seed node 0 ---
    ((unsigned long long*)reach8)[tid] = 0ull;
    if (tid < 2) ((unsigned long long*)(reach8 + NNODES))[tid] = 0ull;
    if (tid == 0) reach8[0] = 1;     // same thread zeroed this word: ordered

    // --- BFS threads load their own 16 nodes' children (overlaps the sync) ---
    int4 la, lb, lc4, ld4, ra, rb, rc4, rd4;
    if (tid < NBFS) {
        const int4* lp = (const int4*)left  + tid * 4;
        const int4* rp = (const int4*)right + tid * 4;
        la = lp[0]; lb = lp[1]; lc4 = lp[2]; ld4 = lp[3];
        ra = rp[0]; rb = rp[1]; rc4 = rp[2]; rd4 = rp[3];
    }

    __syncthreads();                 // uniform: byte map visible to all

    if (tid < NBFS) {
        // pack (L | R<<16) store offsets, leaf (-1) -> DUMMY pad byte
        const int clv[16] = { la.x, la.y, la.z, la.w,  lb.x, lb.y, lb.z, lb.w,
                              lc4.x, lc4.y, lc4.z, lc4.w, ld4.x, ld4.y, ld4.z, ld4.w };
        const int crv[16] = { ra.x, ra.y, ra.z, ra.w,  rb.x, rb.y, rb.z, rb.w,
                              rc4.x, rc4.y, rc4.z, rc4.w, rd4.x, rd4.y, rd4.z, rd4.w };
        unsigned int opk[16];
        #pragma unroll
        for (int j = 0; j < 16; j++) {
            const unsigned int a = (clv[j] >= 0) ? (unsigned int)clv[j] : (unsigned int)DUMMY;
            const unsigned int b = (crv[j] >= 0) ? (unsigned int)crv[j] : (unsigned int)DUMMY;
            opk[j] = a | (b << 16);
        }

        const uint32_t smy =
            (uint32_t)__cvta_generic_to_shared(reach8) + tid * 16;
        volatile unsigned char* vr = (volatile unsigned char*)reach8;

        unsigned long long done0 = 0ull, done1 = 0ull;
        int quiet = 0;

        // first read (post-sync: sees the seed)
        unsigned long long v0, v1;
        asm volatile("ld.volatile.shared.v2.u64 {%0, %1}, [%2];"
                     : "=l"(v0), "=l"(v1) : "r"(smy) : "memory");

        for (;;) {
            const unsigned long long p0 = v0 & ~done0;
            const unsigned long long p1 = v1 & ~done1;
            const int chg = ((p0 | p1) != 0ull);
            if (chg) {
                done0 |= p0;
                done1 |= p1;
                #pragma unroll
                for (int j = 0; j < 8; j++) {
                    const bool p = (p0 >> (8 * j)) & 1u;
                    const unsigned int w = opk[j];
                    const unsigned int a = p ? (w & 0xffffu) : (unsigned int)DUMMY;
                    const unsigned int b = p ? (w >> 16)     : (unsigned int)DUMMY;
                    vr[a] = 1;
                    vr[b] = 1;
                }
                #pragma unroll
                for (int j = 0; j < 8; j++) {
                    const bool p = (p1 >> (8 * j)) & 1u;
                    const unsigned int w = opk[8 + j];
                    const unsigned int a = p ? (w & 0xffffu) : (unsigned int)DUMMY;
                    const unsigned int b = p ? (w >> 16)     : (unsigned int)DUMMY;
                    vr[a] = 1;
                    vr[b] = 1;
                }
            }

            // speculative read for NEXT round: latency hides under bar.red
            unsigned long long n0, n1;
            asm volatile("ld.volatile.shared.v2.u64 {%0, %1}, [%2];"
                         : "=l"(n0), "=l"(n1) : "r"(smy) : "memory");

            unsigned int any;
            asm volatile(
                "{\n\t.reg .pred p, q;\n\t"
                "setp.ne.u32 p, %1, 0;\n\t"
                "bar.red.or.pred q, 2, %2, p;\n\t"
                "selp.u32 %0, 1, 0, q;\n\t}"
                : "=r"(any) : "r"(chg), "r"(NBFS) : "memory");

            if (!any) { if (++quiet == 2) break; }
            else      { quiet = 0; }

            v0 = n0;
            v1 = n1;
        }

        // release the sleepers
        asm volatile("bar.sync 1, %0;" :: "r"(NTHREADS) : "memory");
    } else {
        // sleepers: zero issue pollution during the BFS loop
        asm volatile("bar.sync 1, %0;" :: "r"(NTHREADS) : "memory");
    }

    // --- epilogue (1024-wide): my 8 bytes -> 2x float4 stores ---
    const unsigned long long v = ((volatile unsigned long long*)reach8)[tid];
    float4 o0, o1;
    o0.x = (v & 0x01ull)      ? 1.0f : 0.0f;
    o0.y = (v & (1ull << 8))  ? 1.0f : 0.0f;
    o0.z = (v & (1ull << 16)) ? 1.0f : 0.0f;
    o0.w = (v & (1ull << 24)) ? 1.0f : 0.0f;
    o1.x = (v & (1ull << 32)) ? 1.0f : 0.0f;
    o1.y = (v & (1ull << 40)) ? 1.0f : 0.0f;
    o1.z = (v & (1ull << 48)) ? 1.0f : 0.0f;
    o1.w = (v & (1ull << 56)) ? 1.0f : 0.0f;
    float4* op = (float4*)out + tid * 2;
    op[0] = o0;
    op[1] = o1;
}

extern "C" void kernel_launch(void* const* d_in, const int* in_sizes, int n_in,
                              void* d_out, int out_size)
{
    const int* left  = (const int*)d_in[1];
    const int* right = (const int*)d_in[2];
    float* out = (float*)d_out;

    DAGGenome_reach_kernel<<<1, NTHREADS>>>(left, right, out);
}